// round 14
// baseline (speedup 1.0000x reference)
#include <cuda_runtime.h>
#include <cuda_fp16.h>
#include <math.h>
#include <stdint.h>

// Problem dims
constexpr int kB = 4;
constexpr int kS = 4096;
constexpr int kD = 2048;
constexpr int kM = kB * kS;          // 16384 rows

// GEMM tiling: 128x128x64 CTA tile, 4 warps (2 M x 2 N), warp tile 64x64
constexpr int TM = 128;
constexpr int TN = 128;
constexpr int TK = 64;                              // 64 halves = 128 B rows
constexpr int STAGE_BYTES = (TM + TN) * 128;        // 32 KB
constexpr int STAGES = 3;
constexpr int SMEM_BYTES = STAGES * STAGE_BYTES;    // 96 KB

// Scan blocking
constexpr int NCH = 64;
constexpr int LCH = kS / NCH;        // 64

// Scratch (device globals: allocation-free rule)
__device__ float  g_k[(size_t)kM * kD];       // k (fp32, aux for ewk)
__device__ float  g_e[(size_t)kM * kD];       // ewk
__device__ float  g_r[(size_t)kM * kD];       // r
__device__ float  g_v[(size_t)kM * kD];       // v
__device__ __half g_xh[(size_t)kM * kD];      // x in fp16
__device__ __half g_wh[5][(size_t)kD * kD];   // weights fp16: Wk,Wv,Wr,Ww,Wo
__device__ __half g_yh[(size_t)kM * kD];      // y in fp16
__device__ float  g_carry[(size_t)kB * NCH * 2 * kD];

enum { EPI_NONE = 0, EPI_SIGMOID = 1, EPI_EWK = 2 };

// ---------------------------------------------------------------- helpers
__device__ __forceinline__ uint32_t smem_u32(const void* p) {
    return (uint32_t)__cvta_generic_to_shared(p);
}

// ---------------------------------------------------------------- f32 -> f16
__global__ void f2h_kernel(const float* __restrict__ in,
                           __half* __restrict__ out, int n4) {
    int i = blockIdx.x * blockDim.x + threadIdx.x;
    if (i < n4) {
        float4 v = ((const float4*)in)[i];
        ((__half2*)out)[2 * i]     = __floats2half2_rn(v.x, v.y);
        ((__half2*)out)[2 * i + 1] = __floats2half2_rn(v.z, v.w);
    }
}

// Weight order in g_wh: [Wk, Wv, Wr, Ww, Wo] so KV and RW pairs are contiguous
__global__ void f2h_weights(const float* __restrict__ wk,
                            const float* __restrict__ wv,
                            const float* __restrict__ wr,
                            const float* __restrict__ ww,
                            const float* __restrict__ wo,
                            __half* __restrict__ out, int n4) {
    const float* in;
    switch (blockIdx.y) {
        case 0: in = wk; break;
        case 1: in = wv; break;
        case 2: in = wr; break;
        case 3: in = ww; break;
        default: in = wo; break;
    }
    __half* o = out + (size_t)blockIdx.y * kD * kD;
    int i = blockIdx.x * blockDim.x + threadIdx.x;
    if (i < n4) {
        float4 v = ((const float4*)in)[i];
        ((__half2*)o)[2 * i]     = __floats2half2_rn(v.x, v.y);
        ((__half2*)o)[2 * i + 1] = __floats2half2_rn(v.z, v.w);
    }
}

// ---------------------------------------------------------------- fp16 GEMM
// Two-region GEMM: C[M, 2*2048] = A[M,K] @ W[4096,K]^T where region
// (bn >= 2048) selects output buffer C0/C1 and epilogue E0/E1. Used with
// grid.x = 16 for plain single-output GEMMs (region always 0).
template <int E0, int E1>
__global__ void __launch_bounds__(128, 2)
mma_gemm(const __half* __restrict__ A, const __half* __restrict__ Wt,
         float* __restrict__ C0, float* __restrict__ C1,
         const float* __restrict__ aux, int Kk)
{
    extern __shared__ char smem[];
    const uint32_t smem0 = smem_u32(smem);

    const int tid = threadIdx.x;
    const int wid = tid >> 5;
    const int lane = tid & 31;
    const int g = lane >> 2;          // 0..7
    const int tg = lane & 3;          // 0..3
    const int warpM = wid >> 1;       // 0..1
    const int warpN = wid & 1;        // 0..1
    const int bm = blockIdx.y * TM;
    const int bn = blockIdx.x * TN;   // 0..4095 (weight row space)
    const int region = bn >> 11;      // 0 or 1
    const int bnl = bn & 2047;        // column within the output matrix

    float acc[4][8][4];
#pragma unroll
    for (int a = 0; a < 4; a++)
#pragma unroll
        for (int b = 0; b < 8; b++)
#pragma unroll
            for (int c = 0; c < 4; c++) acc[a][b][c] = 0.f;

    const int nchunk = Kk / TK;       // 32

    // ---- ldmatrix address constants (fragment row & 7 == lane & 7 always)
    const int arow_l = ((lane >> 3) & 1) * 8 + (lane & 7);
    const int akh    = (lane >> 4) & 1;
    const int brow_l = ((lane >> 4) & 1) * 8 + (lane & 7);
    const int bkh    = (lane >> 3) & 1;
    const uint32_t sw = (uint32_t)(lane & 7);

    uint32_t aBase[4];
#pragma unroll
    for (int mi = 0; mi < 4; mi++)
        aBase[mi] = (uint32_t)(warpM * 64 + mi * 16 + arow_l) * 128;
    uint32_t bBase[4];
#pragma unroll
    for (int p = 0; p < 4; p++)
        bBase[p] = (uint32_t)(TM * 128) +
                   (uint32_t)(warpN * 64 + p * 16 + brow_l) * 128;

    uint32_t aOffK[4];
#pragma unroll
    for (int ks = 0; ks < 4; ks++)
        aOffK[ks] = (((uint32_t)(2 * ks + akh)) ^ sw) << 4;
    const uint32_t abXor = ((uint32_t)(akh ^ bkh)) << 4;

    // ---- loader constants
    const int r0 = tid >> 3;          // 0..15
    const int cc = tid & 7;
    const uint32_t lsw = ((uint32_t)(cc ^ (r0 & 7))) << 4;
    const __half* gA0 = A + (size_t)(bm + r0) * Kk + cc * 8;
    const __half* gB0 = Wt + (size_t)(bn + r0) * Kk + cc * 8;
    const uint32_t spA0 = smem0 + (uint32_t)r0 * 128 + lsw;
    const uint32_t spB0 = spA0 + (uint32_t)(TM * 128);
    const size_t rowStride16 = (size_t)16 * Kk;

    auto load_stage = [&](int s, int c) {
        const uint32_t so = (uint32_t)s * STAGE_BYTES;
        const __half* gA = gA0 + (size_t)c * TK;
        const __half* gB = gB0 + (size_t)c * TK;
#pragma unroll
        for (int it = 0; it < 8; it++) {
            asm volatile("cp.async.cg.shared.global [%0], [%1], 16;"
                         :: "r"(spA0 + so + it * 16 * 128),
                            "l"(gA + it * rowStride16));
        }
#pragma unroll
        for (int it = 0; it < 8; it++) {
            asm volatile("cp.async.cg.shared.global [%0], [%1], 16;"
                         :: "r"(spB0 + so + it * 16 * 128),
                            "l"(gB + it * rowStride16));
        }
    };

    load_stage(0, 0);
    asm volatile("cp.async.commit_group;" ::: "memory");
    load_stage(1, 1);
    asm volatile("cp.async.commit_group;" ::: "memory");

    int sc = 0;                       // compute stage
    int sl = 2;                       // load slot

    for (int c = 0; c < nchunk; c++) {
        asm volatile("cp.async.wait_group 1;" ::: "memory");
        __syncthreads();

        const uint32_t st = smem0 + (uint32_t)sc * STAGE_BYTES;

#pragma unroll
        for (int ks = 0; ks < 4; ks++) {
            const uint32_t ao = aOffK[ks];
            const uint32_t bo = ao ^ abXor;
            uint32_t af[4][4];
            uint32_t bf[8][2];
#pragma unroll
            for (int p = 0; p < 4; p++) {
                asm volatile(
                    "ldmatrix.sync.aligned.m8n8.x4.shared.b16 "
                    "{%0,%1,%2,%3}, [%4];"
                    : "=r"(bf[2 * p][0]), "=r"(bf[2 * p][1]),
                      "=r"(bf[2 * p + 1][0]), "=r"(bf[2 * p + 1][1])
                    : "r"(st + bBase[p] + bo));
            }
#pragma unroll
            for (int mi = 0; mi < 4; mi++) {
                asm volatile(
                    "ldmatrix.sync.aligned.m8n8.x4.shared.b16 "
                    "{%0,%1,%2,%3}, [%4];"
                    : "=r"(af[mi][0]), "=r"(af[mi][1]),
                      "=r"(af[mi][2]), "=r"(af[mi][3])
                    : "r"(st + aBase[mi] + ao));
            }
            // Kick the DMA refill after the first LDSM batch is in flight,
            // so chunk-top HMMAs are not delayed behind 16 cp.async issues.
            if (ks == 0) {
                if (c + 2 < nchunk) load_stage(sl, c + 2);
                asm volatile("cp.async.commit_group;" ::: "memory");
            }
#pragma unroll
            for (int mi = 0; mi < 4; mi++)
#pragma unroll
                for (int ni = 0; ni < 8; ni++) {
                    asm volatile(
                        "mma.sync.aligned.m16n8k16.row.col.f32.f16.f16.f32 "
                        "{%0,%1,%2,%3}, {%4,%5,%6,%7}, {%8,%9}, {%0,%1,%2,%3};"
                        : "+f"(acc[mi][ni][0]), "+f"(acc[mi][ni][1]),
                          "+f"(acc[mi][ni][2]), "+f"(acc[mi][ni][3])
                        : "r"(af[mi][0]), "r"(af[mi][1]),
                          "r"(af[mi][2]), "r"(af[mi][3]),
                          "r"(bf[ni][0]), "r"(bf[ni][1]));
                }
        }

        sc = (sc == 2) ? 0 : sc + 1;
        sl = (sl == 2) ? 0 : sl + 1;
    }
    asm volatile("cp.async.wait_group 0;" ::: "memory");

    // ---- epilogue: region-selected output + epilogue op
    float* Cb = (region ? C1 : C0);
#pragma unroll
    for (int mi = 0; mi < 4; mi++) {
#pragma unroll
        for (int ni = 0; ni < 8; ni++) {
            const int n0 = bnl + warpN * 64 + ni * 8 + 2 * tg;
#pragma unroll
            for (int h = 0; h < 2; h++) {
                const int m = bm + warpM * 64 + mi * 16 + g + h * 8;
                float t0 = acc[mi][ni][2 * h];
                float t1 = acc[mi][ni][2 * h + 1];
                const size_t idx = (size_t)m * kD + n0;
                const int epi = region ? E1 : E0;
                if (epi == EPI_SIGMOID) {
                    t0 = 1.f / (1.f + expf(-t0));
                    t1 = 1.f / (1.f + expf(-t1));
                } else if (epi == EPI_EWK) {
                    float2 kk = *(const float2*)(aux + idx);
                    t0 = expf(kk.x - expf(t0));
                    t1 = expf(kk.y - expf(t1));
                }
                float2 o = {t0, t1};
                *(float2*)(Cb + idx) = o;
            }
        }
    }
}

// ---------------------------------------------------------------- blocked scan
__global__ void scan_phase1(const float* __restrict__ ewk,
                            const float* __restrict__ v,
                            const float* __restrict__ td,
                            float* __restrict__ carry)
{
    const int idx = blockIdx.x * blockDim.x + threadIdx.x;  // B*NCH*D
    const int d  = idx & (kD - 1);
    const int ch = (idx >> 11) & (NCH - 1);
    const int b  = idx >> 17;
    const float decay = expf(td[d]);

    float num = 0.f, den = 0.f;
    const size_t base = ((size_t)b * kS + (size_t)ch * LCH) * kD + d;
#pragma unroll 4
    for (int s = 0; s < LCH; s++) {
        const size_t i = base + (size_t)s * kD;
        const float e = ewk[i];
        const float vv = v[i];
        num = decay * num + e * vv;
        den = decay * den + e;
    }
    const size_t ci = (((size_t)b * NCH + ch) * 2) * kD + d;
    carry[ci] = num;
    carry[ci + kD] = den;
}

__global__ void scan_phase2(const float* __restrict__ td,
                            float* __restrict__ carry,
                            float* __restrict__ state_out)
{
    const int idx = blockIdx.x * blockDim.x + threadIdx.x;  // B*D
    const int d = idx & (kD - 1);
    const int b = idx >> 11;
    const float dl = expf(td[d] * (float)LCH);   // decay^LCH

    float num = 0.f, den = 0.f;
    for (int ch = 0; ch < NCH; ch++) {
        const size_t i0 = (((size_t)b * NCH + ch) * 2) * kD + d;
        const float cn = carry[i0];
        const float cd = carry[i0 + kD];
        carry[i0] = num;          // exclusive prefix (state before chunk)
        carry[i0 + kD] = den;
        num = dl * num + cn;
        den = dl * den + cd;
    }
    state_out[(size_t)b * 2 * kD + d] = num;
    state_out[(size_t)b * 2 * kD + kD + d] = den;
}

__global__ void scan_phase3(const float* __restrict__ ewk,
                            const float* __restrict__ v,
                            const float* __restrict__ r,
                            const float* __restrict__ td,
                            const float* __restrict__ carry,
                            __half* __restrict__ y)
{
    const int idx = blockIdx.x * blockDim.x + threadIdx.x;  // B*NCH*D
    const int d  = idx & (kD - 1);
    const int ch = (idx >> 11) & (NCH - 1);
    const int b  = idx >> 17;
    const float decay = expf(td[d]);

    const size_t ci = (((size_t)b * NCH + ch) * 2) * kD + d;
    float num = carry[ci];
    float den = carry[ci + kD];

    const size_t base = ((size_t)b * kS + (size_t)ch * LCH) * kD + d;
#pragma unroll 4
    for (int s = 0; s < LCH; s++) {
        const size_t i = base + (size_t)s * kD;
        const float e = ewk[i];
        const float vv = v[i];
        const float rr = r[i];
        num = decay * num + e * vv;
        den = decay * den + e;
        y[i] = __float2half_rn(rr * (num / (den + 1e-8f)));
    }
}

// ---------------------------------------------------------------- launch
extern "C" void kernel_launch(void* const* d_in, const int* in_sizes, int n_in,
                              void* d_out, int out_size)
{
    const float* x  = (const float*)d_in[0];
    const float* Wr = (const float*)d_in[1];
    const float* Ww = (const float*)d_in[2];
    const float* Wk = (const float*)d_in[3];
    const float* Wv = (const float*)d_in[4];
    const float* Wo = (const float*)d_in[5];
    const float* td = (const float*)d_in[6];
    float* out = (float*)d_out;

    float *bk, *be, *br, *bv, *bcar;
    __half *bxh, *bwh, *byh;
    cudaGetSymbolAddress((void**)&bk,  g_k);
    cudaGetSymbolAddress((void**)&be,  g_e);
    cudaGetSymbolAddress((void**)&br,  g_r);
    cudaGetSymbolAddress((void**)&bv,  g_v);
    cudaGetSymbolAddress((void**)&bxh, g_xh);
    cudaGetSymbolAddress((void**)&bwh, g_wh);
    cudaGetSymbolAddress((void**)&byh, g_yh);
    cudaGetSymbolAddress((void**)&bcar, g_carry);

    __half* wKV = bwh;                               // [Wk; Wv]  (4096 rows)
    __half* wRW = bwh + 2 * (size_t)kD * kD;         // [Wr; Ww]  (4096 rows)
    __half* wO  = bwh + 4 * (size_t)kD * kD;

    cudaFuncSetAttribute((const void*)mma_gemm<EPI_NONE, EPI_NONE>,
                         cudaFuncAttributeMaxDynamicSharedMemorySize, SMEM_BYTES);
    cudaFuncSetAttribute((const void*)mma_gemm<EPI_SIGMOID, EPI_EWK>,
                         cudaFuncAttributeMaxDynamicSharedMemorySize, SMEM_BYTES);

    const int nx4 = (kM / 4) * kD;
    const int nw4 = (kD / 4) * kD;
    f2h_kernel<<<nx4 / 256, 256>>>(x, bxh, nx4);
    dim3 wg(nw4 / 256, 5);
    f2h_weights<<<wg, 256>>>(Wk, Wv, Wr, Ww, Wo, bwh, nw4);

    dim3 ggF(2 * kD / TN, kM / TM);   // (32, 128) fused two-region
    dim3 ggS(kD / TN, kM / TM);       // (16, 128) single-region

    // Fused projections: [k; v] then [r; ewk] (ewk's aux = k, ready)
    mma_gemm<EPI_NONE, EPI_NONE><<<ggF, 128, SMEM_BYTES>>>(
        bxh, wKV, bk, bv, nullptr, kD);
    mma_gemm<EPI_SIGMOID, EPI_EWK><<<ggF, 128, SMEM_BYTES>>>(
        bxh, wRW, br, be, bk, kD);

    // Blocked WKV scan; final state at d_out tail, y in fp16.
    scan_phase1<<<(kB * NCH * kD) / 256, 256>>>(be, bv, td, bcar);
    scan_phase2<<<(kB * kD) / 256, 256>>>(td, bcar, out + (size_t)kM * kD);
    scan_phase3<<<(kB * NCH * kD) / 256, 256>>>(be, bv, br, td, bcar, byh);

    // out = y @ Wo^T
    mma_gemm<EPI_NONE, EPI_NONE><<<ggS, 128, SMEM_BYTES>>>(
        byh, wO, out, nullptr, nullptr, kD);
}

// round 15
// speedup vs baseline: 1.0347x; 1.0347x over previous
#include <cuda_runtime.h>
#include <cuda_fp16.h>
#include <math.h>
#include <stdint.h>

// Problem dims
constexpr int kB = 4;
constexpr int kS = 4096;
constexpr int kD = 2048;
constexpr int kM = kB * kS;          // 16384 rows

// GEMM tiling: 128x128x64 CTA tile, 4 warps (2 M x 2 N), warp tile 64x64
constexpr int TM = 128;
constexpr int TN = 128;
constexpr int TK = 64;                              // 64 halves = 128 B rows
constexpr int STAGE_BYTES = (TM + TN) * 128;        // 32 KB
constexpr int STAGES = 3;
constexpr int SMEM_BYTES = STAGES * STAGE_BYTES;    // 96 KB

// Scan blocking
constexpr int NCH = 64;
constexpr int LCH = kS / NCH;        // 64

// Scratch (device globals: allocation-free rule)
__device__ float  g_e[(size_t)kM * kD];       // ewk
__device__ float  g_r[(size_t)kM * kD];       // r
__device__ float  g_v[(size_t)kM * kD];       // v
__device__ __half g_xh[(size_t)kM * kD];      // x in fp16
__device__ __half g_wh[6][(size_t)kD * kD];   // [Wkw(2x), Wr, Wv, Wo]
__device__ __half g_yh[(size_t)kM * kD];      // y in fp16
__device__ float  g_carry[(size_t)kB * NCH * 2 * kD];

enum { EPI_NONE = 0, EPI_SIGMOID = 1, EPI_KW = 3 };

// ---------------------------------------------------------------- helpers
__device__ __forceinline__ uint32_t smem_u32(const void* p) {
    return (uint32_t)__cvta_generic_to_shared(p);
}

// ---------------------------------------------------------------- f32 -> f16
__global__ void f2h_kernel(const float* __restrict__ in,
                           __half* __restrict__ out, int n4) {
    int i = blockIdx.x * blockDim.x + threadIdx.x;
    if (i < n4) {
        float4 v = ((const float4*)in)[i];
        ((__half2*)out)[2 * i]     = __floats2half2_rn(v.x, v.y);
        ((__half2*)out)[2 * i + 1] = __floats2half2_rn(v.z, v.w);
    }
}

// g_wh layout: rows 0..4095 = interleaved [Wk[n] at 2n, Ww[n] at 2n+1],
// then Wr (offset 2*kD*kD), Wv (3*), Wo (4*). grid.y: 0=Wk,1=Ww,2=Wr,3=Wv,4=Wo.
__global__ void f2h_weights(const float* __restrict__ wk,
                            const float* __restrict__ ww,
                            const float* __restrict__ wr,
                            const float* __restrict__ wv,
                            const float* __restrict__ wo,
                            __half* __restrict__ out, int n4) {
    const int y = blockIdx.y;
    const float* in;
    switch (y) {
        case 0: in = wk; break;
        case 1: in = ww; break;
        case 2: in = wr; break;
        case 3: in = wv; break;
        default: in = wo; break;
    }
    int i = blockIdx.x * blockDim.x + threadIdx.x;
    if (i >= n4) return;
    float4 v = ((const float4*)in)[i];
    __half2 h0 = __floats2half2_rn(v.x, v.y);
    __half2 h1 = __floats2half2_rn(v.z, v.w);

    size_t o4;   // destination float4-equivalent (2x half2) slot
    if (y < 2) {
        // interleave: src row n -> dst row 2n + y
        const int n = (4 * i) / kD;
        const int c = (4 * i) - n * kD;
        o4 = ((size_t)(2 * n + y) * kD + c) / 4;
    } else {
        o4 = (size_t)y * (kD / 4) * kD + i;   // y*kD*kD elements /4
    }
    ((__half2*)out)[2 * o4]     = h0;
    ((__half2*)out)[2 * o4 + 1] = h1;
}

// ---------------------------------------------------------------- fp16 GEMM
// C[M,N] = A[M,K] @ W[N,K]^T, fp16 operands, fp32 accumulate.
// R13 mainloop (best measured). EPI_KW: weight rows are (k,w)-interleaved;
// epilogue folds the pair into ewk = exp(k - exp(w)), one float per pair.
template <int EPI>
__global__ void __launch_bounds__(128, 2)
mma_gemm(const __half* __restrict__ A, const __half* __restrict__ Wt,
         float* __restrict__ C, int Kk)
{
    extern __shared__ char smem[];
    const uint32_t smem0 = smem_u32(smem);

    const int tid = threadIdx.x;
    const int wid = tid >> 5;
    const int lane = tid & 31;
    const int g = lane >> 2;          // 0..7
    const int tg = lane & 3;          // 0..3
    const int warpM = wid >> 1;       // 0..1
    const int warpN = wid & 1;        // 0..1
    const int bm = blockIdx.y * TM;
    const int bn = blockIdx.x * TN;

    float acc[4][8][4];
#pragma unroll
    for (int a = 0; a < 4; a++)
#pragma unroll
        for (int b = 0; b < 8; b++)
#pragma unroll
            for (int c = 0; c < 4; c++) acc[a][b][c] = 0.f;

    const int nchunk = Kk / TK;       // 32

    // ---- ldmatrix address constants (fragment row & 7 == lane & 7 always)
    const int arow_l = ((lane >> 3) & 1) * 8 + (lane & 7);
    const int akh    = (lane >> 4) & 1;
    const int brow_l = ((lane >> 4) & 1) * 8 + (lane & 7);
    const int bkh    = (lane >> 3) & 1;
    const uint32_t sw = (uint32_t)(lane & 7);

    uint32_t aBase[4];
#pragma unroll
    for (int mi = 0; mi < 4; mi++)
        aBase[mi] = (uint32_t)(warpM * 64 + mi * 16 + arow_l) * 128;
    uint32_t bBase[4];
#pragma unroll
    for (int p = 0; p < 4; p++)
        bBase[p] = (uint32_t)(TM * 128) +
                   (uint32_t)(warpN * 64 + p * 16 + brow_l) * 128;

    uint32_t aOffK[4];
#pragma unroll
    for (int ks = 0; ks < 4; ks++)
        aOffK[ks] = (((uint32_t)(2 * ks + akh)) ^ sw) << 4;
    const uint32_t abXor = ((uint32_t)(akh ^ bkh)) << 4;

    // ---- loader constants
    const int r0 = tid >> 3;          // 0..15
    const int cc = tid & 7;
    const uint32_t lsw = ((uint32_t)(cc ^ (r0 & 7))) << 4;
    const __half* gA0 = A + (size_t)(bm + r0) * Kk + cc * 8;
    const __half* gB0 = Wt + (size_t)(bn + r0) * Kk + cc * 8;
    const uint32_t spA0 = smem0 + (uint32_t)r0 * 128 + lsw;
    const uint32_t spB0 = spA0 + (uint32_t)(TM * 128);
    const size_t rowStride16 = (size_t)16 * Kk;

    auto load_stage = [&](int s, int c) {
        const uint32_t so = (uint32_t)s * STAGE_BYTES;
        const __half* gA = gA0 + (size_t)c * TK;
        const __half* gB = gB0 + (size_t)c * TK;
#pragma unroll
        for (int it = 0; it < 8; it++) {
            asm volatile("cp.async.cg.shared.global [%0], [%1], 16;"
                         :: "r"(spA0 + so + it * 16 * 128),
                            "l"(gA + it * rowStride16));
        }
#pragma unroll
        for (int it = 0; it < 8; it++) {
            asm volatile("cp.async.cg.shared.global [%0], [%1], 16;"
                         :: "r"(spB0 + so + it * 16 * 128),
                            "l"(gB + it * rowStride16));
        }
    };

    load_stage(0, 0);
    asm volatile("cp.async.commit_group;" ::: "memory");
    load_stage(1, 1);
    asm volatile("cp.async.commit_group;" ::: "memory");

    int sc = 0;                       // compute stage
    int sl = 2;                       // load slot

    for (int c = 0; c < nchunk; c++) {
        asm volatile("cp.async.wait_group 1;" ::: "memory");
        __syncthreads();

        const uint32_t st = smem0 + (uint32_t)sc * STAGE_BYTES;

        // Kick the DMA refill, then compute the chunk (R13 placement)
        if (c + 2 < nchunk) load_stage(sl, c + 2);
        asm volatile("cp.async.commit_group;" ::: "memory");

#pragma unroll
        for (int ks = 0; ks < 4; ks++) {
            const uint32_t ao = aOffK[ks];
            const uint32_t bo = ao ^ abXor;
            uint32_t af[4][4];
            uint32_t bf[8][2];
#pragma unroll
            for (int p = 0; p < 4; p++) {
                asm volatile(
                    "ldmatrix.sync.aligned.m8n8.x4.shared.b16 "
                    "{%0,%1,%2,%3}, [%4];"
                    : "=r"(bf[2 * p][0]), "=r"(bf[2 * p][1]),
                      "=r"(bf[2 * p + 1][0]), "=r"(bf[2 * p + 1][1])
                    : "r"(st + bBase[p] + bo));
            }
#pragma unroll
            for (int mi = 0; mi < 4; mi++) {
                asm volatile(
                    "ldmatrix.sync.aligned.m8n8.x4.shared.b16 "
                    "{%0,%1,%2,%3}, [%4];"
                    : "=r"(af[mi][0]), "=r"(af[mi][1]),
                      "=r"(af[mi][2]), "=r"(af[mi][3])
                    : "r"(st + aBase[mi] + ao));
            }
#pragma unroll
            for (int mi = 0; mi < 4; mi++)
#pragma unroll
                for (int ni = 0; ni < 8; ni++) {
                    asm volatile(
                        "mma.sync.aligned.m16n8k16.row.col.f32.f16.f16.f32 "
                        "{%0,%1,%2,%3}, {%4,%5,%6,%7}, {%8,%9}, {%0,%1,%2,%3};"
                        : "+f"(acc[mi][ni][0]), "+f"(acc[mi][ni][1]),
                          "+f"(acc[mi][ni][2]), "+f"(acc[mi][ni][3])
                        : "r"(af[mi][0]), "r"(af[mi][1]),
                          "r"(af[mi][2]), "r"(af[mi][3]),
                          "r"(bf[ni][0]), "r"(bf[ni][1]));
                }
        }

        sc = (sc == 2) ? 0 : sc + 1;
        sl = (sl == 2) ? 0 : sl + 1;
    }
    asm volatile("cp.async.wait_group 0;" ::: "memory");

    // ---- epilogue (fragment: c0,c1 = row g; c2,c3 = row g+8; cols 2tg,2tg+1)
#pragma unroll
    for (int mi = 0; mi < 4; mi++) {
#pragma unroll
        for (int ni = 0; ni < 8; ni++) {
#pragma unroll
            for (int h = 0; h < 2; h++) {
                const int m = bm + warpM * 64 + mi * 16 + g + h * 8;
                float t0 = acc[mi][ni][2 * h];
                float t1 = acc[mi][ni][2 * h + 1];
                if (EPI == EPI_KW) {
                    // cols (2n, 2n+1) = (k_n, w_n); write ewk at logical n
                    const int lc = (bn >> 1) + warpN * 32 + ni * 4 + tg;
                    C[(size_t)m * kD + lc] = expf(t0 - expf(t1));
                } else {
                    const int n0 = bn + warpN * 64 + ni * 8 + 2 * tg;
                    const size_t idx = (size_t)m * kD + n0;
                    if (EPI == EPI_SIGMOID) {
                        t0 = 1.f / (1.f + expf(-t0));
                        t1 = 1.f / (1.f + expf(-t1));
                    }
                    float2 o = {t0, t1};
                    *(float2*)(C + idx) = o;
                }
            }
        }
    }
}

// ---------------------------------------------------------------- blocked scan
__global__ void scan_phase1(const float* __restrict__ ewk,
                            const float* __restrict__ v,
                            const float* __restrict__ td,
                            float* __restrict__ carry)
{
    const int idx = blockIdx.x * blockDim.x + threadIdx.x;  // B*NCH*D
    const int d  = idx & (kD - 1);
    const int ch = (idx >> 11) & (NCH - 1);
    const int b  = idx >> 17;
    const float decay = expf(td[d]);

    float num = 0.f, den = 0.f;
    const size_t base = ((size_t)b * kS + (size_t)ch * LCH) * kD + d;
#pragma unroll 4
    for (int s = 0; s < LCH; s++) {
        const size_t i = base + (size_t)s * kD;
        const float e = ewk[i];
        const float vv = v[i];
        num = decay * num + e * vv;
        den = decay * den + e;
    }
    const size_t ci = (((size_t)b * NCH + ch) * 2) * kD + d;
    carry[ci] = num;
    carry[ci + kD] = den;
}

__global__ void scan_phase2(const float* __restrict__ td,
                            float* __restrict__ carry,
                            float* __restrict__ state_out)
{
    const int idx = blockIdx.x * blockDim.x + threadIdx.x;  // B*D
    const int d = idx & (kD - 1);
    const int b = idx >> 11;
    const float dl = expf(td[d] * (float)LCH);   // decay^LCH

    float num = 0.f, den = 0.f;
    for (int ch = 0; ch < NCH; ch++) {
        const size_t i0 = (((size_t)b * NCH + ch) * 2) * kD + d;
        const float cn = carry[i0];
        const float cd = carry[i0 + kD];
        carry[i0] = num;          // exclusive prefix (state before chunk)
        carry[i0 + kD] = den;
        num = dl * num + cn;
        den = dl * den + cd;
    }
    state_out[(size_t)b * 2 * kD + d] = num;
    state_out[(size_t)b * 2 * kD + kD + d] = den;
}

__global__ void scan_phase3(const float* __restrict__ ewk,
                            const float* __restrict__ v,
                            const float* __restrict__ r,
                            const float* __restrict__ td,
                            const float* __restrict__ carry,
                            __half* __restrict__ y)
{
    const int idx = blockIdx.x * blockDim.x + threadIdx.x;  // B*NCH*D
    const int d  = idx & (kD - 1);
    const int ch = (idx >> 11) & (NCH - 1);
    const int b  = idx >> 17;
    const float decay = expf(td[d]);

    const size_t ci = (((size_t)b * NCH + ch) * 2) * kD + d;
    float num = carry[ci];
    float den = carry[ci + kD];

    const size_t base = ((size_t)b * kS + (size_t)ch * LCH) * kD + d;
#pragma unroll 4
    for (int s = 0; s < LCH; s++) {
        const size_t i = base + (size_t)s * kD;
        const float e = ewk[i];
        const float vv = v[i];
        const float rr = r[i];
        num = decay * num + e * vv;
        den = decay * den + e;
        y[i] = __float2half_rn(rr * (num / (den + 1e-8f)));
    }
}

// ---------------------------------------------------------------- launch
extern "C" void kernel_launch(void* const* d_in, const int* in_sizes, int n_in,
                              void* d_out, int out_size)
{
    const float* x  = (const float*)d_in[0];
    const float* Wr = (const float*)d_in[1];
    const float* Ww = (const float*)d_in[2];
    const float* Wk = (const float*)d_in[3];
    const float* Wv = (const float*)d_in[4];
    const float* Wo = (const float*)d_in[5];
    const float* td = (const float*)d_in[6];
    float* out = (float*)d_out;

    float *be, *br, *bv, *bcar;
    __half *bxh, *bwh, *byh;
    cudaGetSymbolAddress((void**)&be,  g_e);
    cudaGetSymbolAddress((void**)&br,  g_r);
    cudaGetSymbolAddress((void**)&bv,  g_v);
    cudaGetSymbolAddress((void**)&bxh, g_xh);
    cudaGetSymbolAddress((void**)&bwh, g_wh);
    cudaGetSymbolAddress((void**)&byh, g_yh);
    cudaGetSymbolAddress((void**)&bcar, g_carry);

    __half* wKW = bwh;                               // interleaved, 4096 rows
    __half* wR  = bwh + 2 * (size_t)kD * kD;
    __half* wV  = bwh + 3 * (size_t)kD * kD;
    __half* wO  = bwh + 4 * (size_t)kD * kD;

    cudaFuncSetAttribute((const void*)mma_gemm<EPI_NONE>,
                         cudaFuncAttributeMaxDynamicSharedMemorySize, SMEM_BYTES);
    cudaFuncSetAttribute((const void*)mma_gemm<EPI_SIGMOID>,
                         cudaFuncAttributeMaxDynamicSharedMemorySize, SMEM_BYTES);
    cudaFuncSetAttribute((const void*)mma_gemm<EPI_KW>,
                         cudaFuncAttributeMaxDynamicSharedMemorySize, SMEM_BYTES);

    const int nx4 = (kM / 4) * kD;
    const int nw4 = (kD / 4) * kD;
    f2h_kernel<<<nx4 / 256, 256>>>(x, bxh, nx4);                     // 0
    dim3 wg(nw4 / 256, 5);
    f2h_weights<<<wg, 256>>>(Wk, Ww, Wr, Wv, Wo, bwh, nw4);          // 1

    dim3 ggKW(2 * kD / TN, kM / TM);  // (32, 128)
    dim3 ggS(kD / TN, kM / TM);       // (16, 128)

    // 2: ewk = exp(k - exp(w)) via interleaved KW GEMM (no k buffer at all)
    mma_gemm<EPI_KW><<<ggKW, 128, SMEM_BYTES>>>(bxh, wKW, be, kD);
    // 3: v
    mma_gemm<EPI_NONE><<<ggS, 128, SMEM_BYTES>>>(bxh, wV, bv, kD);
    // 4: scan phase 1 (needs ewk, v)
    scan_phase1<<<(kB * NCH * kD) / 256, 256>>>(be, bv, td, bcar);
    // 5: r (ncu -s 5 window lands here)
    mma_gemm<EPI_SIGMOID><<<ggS, 128, SMEM_BYTES>>>(bxh, wR, br, kD);
    // 6,7: scan phases 2,3 (phase 3 needs r)
    scan_phase2<<<(kB * kD) / 256, 256>>>(td, bcar, out + (size_t)kM * kD);
    scan_phase3<<<(kB * NCH * kD) / 256, 256>>>(be, bv, br, td, bcar, byh);
    // 8: out = y @ Wo^T
    mma_gemm<EPI_NONE><<<ggS, 128, SMEM_BYTES>>>(byh, wO, out, kD);
}